// round 1
// baseline (speedup 1.0000x reference)
#include <cuda_runtime.h>
#include <cuda_bf16.h>
#include <math.h>

#define N_NODES   50000
#define N_EDGES   800000
#define IN_FEATS  256
#define HID       64
#define HEADS     3
#define HD        192   // HEADS*HID
#define OUT_FEATS 64
#define NEG_SLOPE 0.2f

// ---------------- device scratch (no allocs allowed) ----------------
__device__ float g_feat[(size_t)N_NODES * HD];   // per-layer projected features
__device__ float g_x[(size_t)N_NODES * HD];      // layer outputs (reused)
__device__ float g_hid[(size_t)N_NODES * HID];   // MLP hidden
__device__ float g_el[(size_t)N_NODES * HEADS];
__device__ float g_er[(size_t)N_NODES * HEADS];
__device__ int   g_rowptr[N_NODES + 1];
__device__ int   g_cnt[N_NODES];
__device__ int   g_srcs[N_EDGES];                // src node ids sorted by dst

// ---------------- CSR build ----------------
__global__ void hist_k(const int* __restrict__ dst) {
    int e = blockIdx.x * blockDim.x + threadIdx.x;
    if (e < N_EDGES) atomicAdd(&g_cnt[dst[e]], 1);
}

__global__ void scan_k() {
    __shared__ int part[1024];
    int t = threadIdx.x;
    const int chunk = (N_NODES + 1023) / 1024;  // 49
    int beg = t * chunk;
    int end = min(beg + chunk, N_NODES);
    int s = 0;
    for (int i = beg; i < end; i++) s += g_cnt[i];
    part[t] = s;
    __syncthreads();
    for (int off = 1; off < 1024; off <<= 1) {
        int v = 0;
        if (t >= off) v = part[t - off];
        __syncthreads();
        part[t] += v;
        __syncthreads();
    }
    int run = (t == 0) ? 0 : part[t - 1];
    for (int i = beg; i < end; i++) { g_rowptr[i] = run; run += g_cnt[i]; }
    if (t == 1023) g_rowptr[N_NODES] = part[1023];
}

__global__ void scatter_k(const int* __restrict__ src, const int* __restrict__ dst) {
    int e = blockIdx.x * blockDim.x + threadIdx.x;
    if (e < N_EDGES) {
        int d = dst[e];
        int pos = atomicAdd(&g_cnt[d], 1);
        g_srcs[g_rowptr[d] + pos] = src[e];
    }
}

// ---------------- SGEMM: C[M,N] = A[M,K] @ B[K,N] (+bias)(+relu) ----------------
// BM=64 BN=64 BK=16, 256 threads, 4x4 micro-tile. K % 16 == 0, N % 64 == 0 (or N<=64 with grid.y=1).
__global__ void sgemm_k(const float* __restrict__ A, const float* __restrict__ B,
                        float* __restrict__ C, int M, int N, int K,
                        const float* __restrict__ bias, int act) {
    __shared__ float As[16][65];
    __shared__ float Bs[16][64];
    int tid = threadIdx.x;
    int tx = tid & 15, ty = tid >> 4;
    int bm = blockIdx.x * 64, bn = blockIdx.y * 64;
    float acc[4][4] = {};

    int ar = tid >> 2, ac4 = (tid & 3) << 2;   // A: one float4 per thread
    for (int k0 = 0; k0 < K; k0 += 16) {
        int gr = bm + ar;
        float4 av = make_float4(0.f, 0.f, 0.f, 0.f);
        if (gr < M) av = *(const float4*)&A[(size_t)gr * K + k0 + ac4];
        As[ac4 + 0][ar] = av.x;
        As[ac4 + 1][ar] = av.y;
        As[ac4 + 2][ar] = av.z;
        As[ac4 + 3][ar] = av.w;
#pragma unroll
        for (int i = 0; i < 4; i++) {
            int idx = tid + i * 256;
            int br = idx >> 6, bc = idx & 63;
            Bs[br][bc] = B[(size_t)(k0 + br) * N + bn + bc];
        }
        __syncthreads();
#pragma unroll
        for (int k = 0; k < 16; k++) {
            float ra[4], rb[4];
#pragma unroll
            for (int m = 0; m < 4; m++) ra[m] = As[k][ty * 4 + m];
#pragma unroll
            for (int n = 0; n < 4; n++) rb[n] = Bs[k][tx * 4 + n];
#pragma unroll
            for (int m = 0; m < 4; m++)
#pragma unroll
                for (int n = 0; n < 4; n++) acc[m][n] += ra[m] * rb[n];
        }
        __syncthreads();
    }
#pragma unroll
    for (int m = 0; m < 4; m++) {
        int gr = bm + ty * 4 + m;
        if (gr >= M) continue;
#pragma unroll
        for (int n = 0; n < 4; n++) {
            int gc = bn + tx * 4 + n;
            float v = acc[m][n];
            if (bias) v += bias[gc];
            if (act) v = fmaxf(v, 0.f);
            C[(size_t)gr * N + gc] = v;
        }
    }
}

// ---------------- per-node attention projections el, er ----------------
__global__ void attn_proj_k(const float* __restrict__ feat,
                            const float* __restrict__ al, const float* __restrict__ ar) {
    int warp = (blockIdx.x * blockDim.x + threadIdx.x) >> 5;
    int lane = threadIdx.x & 31;
    if (warp >= N_NODES) return;
    const float* f = feat + (size_t)warp * HD;
    float pl[3] = {0.f, 0.f, 0.f}, pr[3] = {0.f, 0.f, 0.f};
#pragma unroll
    for (int k = 0; k < 6; k++) {
        int idx = lane + 32 * k;
        float v = f[idx];
        int h = k >> 1;
        pl[h] += v * al[idx];
        pr[h] += v * ar[idx];
    }
#pragma unroll
    for (int off = 16; off; off >>= 1) {
#pragma unroll
        for (int h = 0; h < 3; h++) {
            pl[h] += __shfl_xor_sync(0xFFFFFFFFu, pl[h], off);
            pr[h] += __shfl_xor_sync(0xFFFFFFFFu, pr[h], off);
        }
    }
    if (lane == 0) {
#pragma unroll
        for (int h = 0; h < 3; h++) {
            g_el[warp * 3 + h] = pl[h];
            g_er[warp * 3 + h] = pr[h];
        }
    }
}

__device__ __forceinline__ float leaky(float x) { return x > 0.f ? x : NEG_SLOPE * x; }

// ---------------- edge-softmax + aggregation: one warp per dst node ----------------
__global__ void agg_k(const float* __restrict__ feat, const float* __restrict__ bias,
                      float* __restrict__ out) {
    int warp = (blockIdx.x * blockDim.x + threadIdx.x) >> 5;
    int lane = threadIdx.x & 31;
    if (warp >= N_NODES) return;
    int beg = g_rowptr[warp], end = g_rowptr[warp + 1];
    float er0 = g_er[warp * 3 + 0];
    float er1 = g_er[warp * 3 + 1];
    float er2 = g_er[warp * 3 + 2];

    // pass 1: per-head max over incoming edges (lanes parallel over edges)
    float m0 = -1e30f, m1 = -1e30f, m2 = -1e30f;
    for (int i = beg + lane; i < end; i += 32) {
        int s = g_srcs[i];
        float e0 = leaky(g_el[s * 3 + 0] + er0);
        float e1 = leaky(g_el[s * 3 + 1] + er1);
        float e2 = leaky(g_el[s * 3 + 2] + er2);
        m0 = fmaxf(m0, e0); m1 = fmaxf(m1, e1); m2 = fmaxf(m2, e2);
    }
#pragma unroll
    for (int off = 16; off; off >>= 1) {
        m0 = fmaxf(m0, __shfl_xor_sync(0xFFFFFFFFu, m0, off));
        m1 = fmaxf(m1, __shfl_xor_sync(0xFFFFFFFFu, m1, off));
        m2 = fmaxf(m2, __shfl_xor_sync(0xFFFFFFFFu, m2, off));
    }

    // pass 2: weighted accumulation. Each lane owns 6 of the 192 feature slots.
    int base = lane * 6;
    int h0 = (base + 0) >> 6, h1 = (base + 1) >> 6, h2 = (base + 2) >> 6;
    int h3 = (base + 3) >> 6, h4 = (base + 4) >> 6, h5 = (base + 5) >> 6;
    float acc0 = 0.f, acc1 = 0.f, acc2 = 0.f, acc3 = 0.f, acc4 = 0.f, acc5 = 0.f;
    float s0 = 0.f, s1 = 0.f, s2 = 0.f;
    for (int i = beg; i < end; i++) {
        int s = g_srcs[i];  // broadcast load (same addr all lanes)
        float w0 = __expf(leaky(g_el[s * 3 + 0] + er0) - m0);
        float w1 = __expf(leaky(g_el[s * 3 + 1] + er1) - m1);
        float w2 = __expf(leaky(g_el[s * 3 + 2] + er2) - m2);
        s0 += w0; s1 += w1; s2 += w2;
        const float* fp = feat + (size_t)s * HD + base;
        float2 v0 = *(const float2*)(fp + 0);
        float2 v1 = *(const float2*)(fp + 2);
        float2 v2 = *(const float2*)(fp + 4);
        float wa0 = h0 == 0 ? w0 : (h0 == 1 ? w1 : w2);
        float wa1 = h1 == 0 ? w0 : (h1 == 1 ? w1 : w2);
        float wa2 = h2 == 0 ? w0 : (h2 == 1 ? w1 : w2);
        float wa3 = h3 == 0 ? w0 : (h3 == 1 ? w1 : w2);
        float wa4 = h4 == 0 ? w0 : (h4 == 1 ? w1 : w2);
        float wa5 = h5 == 0 ? w0 : (h5 == 1 ? w1 : w2);
        acc0 += wa0 * v0.x; acc1 += wa1 * v0.y;
        acc2 += wa2 * v1.x; acc3 += wa3 * v1.y;
        acc4 += wa4 * v2.x; acc5 += wa5 * v2.y;
    }
    float i0 = 0.f, i1 = 0.f, i2 = 0.f;
    if (end > beg) { i0 = 1.f / s0; i1 = 1.f / s1; i2 = 1.f / s2; }
    float ia0 = h0 == 0 ? i0 : (h0 == 1 ? i1 : i2);
    float ia1 = h1 == 0 ? i0 : (h1 == 1 ? i1 : i2);
    float ia2 = h2 == 0 ? i0 : (h2 == 1 ? i1 : i2);
    float ia3 = h3 == 0 ? i0 : (h3 == 1 ? i1 : i2);
    float ia4 = h4 == 0 ? i0 : (h4 == 1 ? i1 : i2);
    float ia5 = h5 == 0 ? i0 : (h5 == 1 ? i1 : i2);
    float* op = out + (size_t)warp * HD + base;
    op[0] = fmaxf(acc0 * ia0 + bias[base + 0], 0.f);
    op[1] = fmaxf(acc1 * ia1 + bias[base + 1], 0.f);
    op[2] = fmaxf(acc2 * ia2 + bias[base + 2], 0.f);
    op[3] = fmaxf(acc3 * ia3 + bias[base + 3], 0.f);
    op[4] = fmaxf(acc4 * ia4 + bias[base + 4], 0.f);
    op[5] = fmaxf(acc5 * ia5 + bias[base + 5], 0.f);
}

// ---------------- host launch ----------------
extern "C" void kernel_launch(void* const* d_in, const int* in_sizes, int n_in,
                              void* d_out, int out_size) {
    const float* features = (const float*)d_in[0];
    const int*   src      = (const int*)d_in[1];
    const int*   dst      = (const int*)d_in[2];
    const float* W1  = (const float*)d_in[3];
    const float* al1 = (const float*)d_in[4];
    const float* ar1 = (const float*)d_in[5];
    const float* b1  = (const float*)d_in[6];
    const float* W2  = (const float*)d_in[7];
    const float* al2 = (const float*)d_in[8];
    const float* ar2 = (const float*)d_in[9];
    const float* b2  = (const float*)d_in[10];
    const float* Wm1 = (const float*)d_in[11];
    const float* bm1 = (const float*)d_in[12];
    const float* Wm2 = (const float*)d_in[13];
    const float* bm2 = (const float*)d_in[14];
    float* out = (float*)d_out;

    float *feat, *x, *hid;
    int *cnt;
    cudaGetSymbolAddress((void**)&feat, g_feat);
    cudaGetSymbolAddress((void**)&x, g_x);
    cudaGetSymbolAddress((void**)&hid, g_hid);
    cudaGetSymbolAddress((void**)&cnt, g_cnt);

    const int EB = (N_EDGES + 255) / 256;
    const int WB = (N_NODES * 32 + 255) / 256;  // one warp per node, 256-thread blocks
    const int GM = (N_NODES + 63) / 64;

    // CSR build (graph is the same for both layers)
    cudaMemsetAsync(cnt, 0, N_NODES * sizeof(int));
    hist_k<<<EB, 256>>>(dst);
    scan_k<<<1, 1024>>>();
    cudaMemsetAsync(cnt, 0, N_NODES * sizeof(int));
    scatter_k<<<EB, 256>>>(src, dst);

    // ---- GAT layer 1 ----
    sgemm_k<<<dim3(GM, 3), 256>>>(features, W1, feat, N_NODES, HD, IN_FEATS, nullptr, 0);
    attn_proj_k<<<WB, 256>>>(feat, al1, ar1);
    agg_k<<<WB, 256>>>(feat, b1, x);

    // ---- GAT layer 2 ----
    sgemm_k<<<dim3(GM, 3), 256>>>(x, W2, feat, N_NODES, HD, HD, nullptr, 0);
    attn_proj_k<<<WB, 256>>>(feat, al2, ar2);
    agg_k<<<WB, 256>>>(feat, b2, x);

    // ---- MLP head ----
    sgemm_k<<<dim3(GM, 1), 256>>>(x, Wm1, hid, N_NODES, HID, HD, bm1, 1);
    sgemm_k<<<dim3(GM, 1), 256>>>(hid, Wm2, out, N_NODES, OUT_FEATS, HID, bm2, 0);
}

// round 2
// speedup vs baseline: 1.1429x; 1.1429x over previous
#include <cuda_runtime.h>
#include <cuda_bf16.h>
#include <math.h>

#define N_NODES   50000
#define N_EDGES   800000
#define IN_FEATS  256
#define HID       64
#define HEADS     3
#define HD        192   // HEADS*HID
#define OUT_FEATS 64
#define NEG_SLOPE 0.2f

// ---------------- device scratch (no allocs allowed) ----------------
__device__ float g_feat[(size_t)N_NODES * HD];   // per-layer projected features
__device__ float g_x[(size_t)N_NODES * HD];      // layer outputs (reused)
__device__ float g_hid[(size_t)N_NODES * HID];   // MLP hidden
__device__ float g_el[(size_t)N_NODES * HEADS];
__device__ float g_er[(size_t)N_NODES * HEADS];
__device__ int   g_rowptr[N_NODES + 1];
__device__ int   g_cnt[N_NODES];
__device__ int   g_srcs[N_EDGES];                // src node ids sorted by dst

// ---------------- CSR build ----------------
__global__ void hist_k(const int* __restrict__ dst) {
    int e = blockIdx.x * blockDim.x + threadIdx.x;
    if (e < N_EDGES) atomicAdd(&g_cnt[dst[e]], 1);
}

__global__ void scan_k() {
    __shared__ int part[1024];
    int t = threadIdx.x;
    const int chunk = (N_NODES + 1023) / 1024;  // 49
    int beg = t * chunk;
    int end = min(beg + chunk, N_NODES);
    int s = 0;
    for (int i = beg; i < end; i++) s += g_cnt[i];
    part[t] = s;
    __syncthreads();
    for (int off = 1; off < 1024; off <<= 1) {
        int v = 0;
        if (t >= off) v = part[t - off];
        __syncthreads();
        part[t] += v;
        __syncthreads();
    }
    int run = (t == 0) ? 0 : part[t - 1];
    for (int i = beg; i < end; i++) { g_rowptr[i] = run; run += g_cnt[i]; }
    if (t == 1023) g_rowptr[N_NODES] = part[1023];
}

__global__ void scatter_k(const int* __restrict__ src, const int* __restrict__ dst) {
    int e = blockIdx.x * blockDim.x + threadIdx.x;
    if (e < N_EDGES) {
        int d = dst[e];
        int pos = atomicAdd(&g_cnt[d], 1);
        g_srcs[g_rowptr[d] + pos] = src[e];
    }
}

// ---------------- SGEMM 128x64 tile, 8x8 microtile, 128 threads ----------------
// C[M,N] = A[M,K] @ B[K,N] (+bias)(+relu). BN=64 per blockIdx.y.
// If al != null: additionally write g_el/g_er for head = blockIdx.y (GAT layers,
// where the 64-col block == one head's feature slice).
__global__ void __launch_bounds__(128)
gemm_k(const float* __restrict__ A, const float* __restrict__ B,
       float* __restrict__ C, int M, int N, int K,
       const float* __restrict__ bias, int act,
       const float* __restrict__ al, const float* __restrict__ ar) {
    __shared__ float As[16][128];   // [k][m]
    __shared__ float Bs[16][64];    // [k][n]
    const int tid = threadIdx.x;
    const int tm = tid >> 3;        // 0..15
    const int tn = tid & 7;         // 0..7
    const int bm = blockIdx.x * 128;
    const int bn = blockIdx.y * 64;

    float acc[8][8];
#pragma unroll
    for (int i = 0; i < 8; i++)
#pragma unroll
        for (int j = 0; j < 8; j++) acc[i][j] = 0.f;

    const int garow = bm + tid;                 // each thread loads one A row
    const float* aptr = A + (size_t)garow * K;
    const bool arow_ok = garow < M;

    for (int k0 = 0; k0 < K; k0 += 16) {
        // A: 4 float4 along K for this thread's row, stored transposed
        float4 av[4];
#pragma unroll
        for (int i = 0; i < 4; i++)
            av[i] = arow_ok ? *(const float4*)(aptr + k0 + i * 4)
                            : make_float4(0.f, 0.f, 0.f, 0.f);
#pragma unroll
        for (int i = 0; i < 4; i++) {
            As[i * 4 + 0][tid] = av[i].x;
            As[i * 4 + 1][tid] = av[i].y;
            As[i * 4 + 2][tid] = av[i].z;
            As[i * 4 + 3][tid] = av[i].w;
        }
        // B: 2 float4 per thread
#pragma unroll
        for (int i = 0; i < 2; i++) {
            int fid = tid + i * 128;
            int br = fid >> 4, c4 = (fid & 15) << 2;
            *(float4*)&Bs[br][c4] = *(const float4*)&B[(size_t)(k0 + br) * N + bn + c4];
        }
        __syncthreads();
#pragma unroll
        for (int k = 0; k < 16; k++) {
            float4 a0 = *(const float4*)&As[k][tm * 4];
            float4 a1 = *(const float4*)&As[k][tm * 4 + 64];
            float4 b0 = *(const float4*)&Bs[k][tn * 4];
            float4 b1 = *(const float4*)&Bs[k][tn * 4 + 32];
            float ra[8] = {a0.x, a0.y, a0.z, a0.w, a1.x, a1.y, a1.z, a1.w};
            float rb[8] = {b0.x, b0.y, b0.z, b0.w, b1.x, b1.y, b1.z, b1.w};
#pragma unroll
            for (int i = 0; i < 8; i++)
#pragma unroll
                for (int j = 0; j < 8; j++) acc[i][j] += ra[i] * rb[j];
        }
        __syncthreads();
    }

    // epilogue
    float elp[8], erp[8];
    float alv[8], arv[8];
    const int head = blockIdx.y;
    if (al) {
#pragma unroll
        for (int j = 0; j < 8; j++) {
            int c = tn * 4 + ((j < 4) ? j : 32 + (j - 4));
            alv[j] = __ldg(&al[head * 64 + c]);
            arv[j] = __ldg(&ar[head * 64 + c]);
        }
#pragma unroll
        for (int i = 0; i < 8; i++) { elp[i] = 0.f; erp[i] = 0.f; }
    }
    float bv[8];
    if (bias) {
#pragma unroll
        for (int j = 0; j < 8; j++) {
            int c = tn * 4 + ((j < 4) ? j : 32 + (j - 4));
            bv[j] = __ldg(&bias[bn + c]);
        }
    }
#pragma unroll
    for (int i = 0; i < 8; i++) {
        int gr = bm + tm * 4 + ((i < 4) ? i : 64 + (i - 4));
        float v[8];
#pragma unroll
        for (int j = 0; j < 8; j++) {
            float t = acc[i][j];
            if (bias) t += bv[j];
            if (act) t = fmaxf(t, 0.f);
            v[j] = t;
            if (al) { elp[i] += t * alv[j]; erp[i] += t * arv[j]; }
        }
        if (gr < M) {
            float* cp = C + (size_t)gr * N + bn;
            *(float4*)(cp + tn * 4)      = make_float4(v[0], v[1], v[2], v[3]);
            *(float4*)(cp + tn * 4 + 32) = make_float4(v[4], v[5], v[6], v[7]);
        }
    }
    if (al) {
        // reduce over tn (lane bits 0..2)
#pragma unroll
        for (int off = 1; off < 8; off <<= 1) {
#pragma unroll
            for (int i = 0; i < 8; i++) {
                elp[i] += __shfl_xor_sync(0xFFFFFFFFu, elp[i], off);
                erp[i] += __shfl_xor_sync(0xFFFFFFFFu, erp[i], off);
            }
        }
        if (tn == 0) {
#pragma unroll
            for (int i = 0; i < 8; i++) {
                int gr = bm + tm * 4 + ((i < 4) ? i : 64 + (i - 4));
                if (gr < M) {
                    g_el[gr * 3 + head] = elp[i];
                    g_er[gr * 3 + head] = erp[i];
                }
            }
        }
    }
}

__device__ __forceinline__ float leaky(float x) { return x > 0.f ? x : NEG_SLOPE * x; }

// ---------------- edge-softmax + aggregation: one warp per dst node ----------------
__global__ void agg_k(const float* __restrict__ feat, const float* __restrict__ bias,
                      float* __restrict__ out) {
    int warp = (blockIdx.x * blockDim.x + threadIdx.x) >> 5;
    int lane = threadIdx.x & 31;
    if (warp >= N_NODES) return;
    int beg = g_rowptr[warp], end = g_rowptr[warp + 1];
    float er0 = g_er[warp * 3 + 0];
    float er1 = g_er[warp * 3 + 1];
    float er2 = g_er[warp * 3 + 2];

    // pass 1: per-head max over incoming edges (lanes parallel over edges)
    float m0 = -1e30f, m1 = -1e30f, m2 = -1e30f;
    for (int i = beg + lane; i < end; i += 32) {
        int s = g_srcs[i];
        m0 = fmaxf(m0, leaky(g_el[s * 3 + 0] + er0));
        m1 = fmaxf(m1, leaky(g_el[s * 3 + 1] + er1));
        m2 = fmaxf(m2, leaky(g_el[s * 3 + 2] + er2));
    }
#pragma unroll
    for (int off = 16; off; off >>= 1) {
        m0 = fmaxf(m0, __shfl_xor_sync(0xFFFFFFFFu, m0, off));
        m1 = fmaxf(m1, __shfl_xor_sync(0xFFFFFFFFu, m1, off));
        m2 = fmaxf(m2, __shfl_xor_sync(0xFFFFFFFFu, m2, off));
    }

    // pass 2: weighted accumulation. Each lane owns 6 of the 192 feature slots.
    int base = lane * 6;
    int h0 = (base + 0) >> 6, h1 = (base + 1) >> 6, h2 = (base + 2) >> 6;
    int h3 = (base + 3) >> 6, h4 = (base + 4) >> 6, h5 = (base + 5) >> 6;
    float acc0 = 0.f, acc1 = 0.f, acc2 = 0.f, acc3 = 0.f, acc4 = 0.f, acc5 = 0.f;
    float s0 = 0.f, s1 = 0.f, s2 = 0.f;
    int sNext = (beg < end) ? g_srcs[beg] : 0;
    for (int i = beg; i < end; i++) {
        int s = sNext;
        if (i + 1 < end) sNext = g_srcs[i + 1];
        float w0 = __expf(leaky(g_el[s * 3 + 0] + er0) - m0);
        float w1 = __expf(leaky(g_el[s * 3 + 1] + er1) - m1);
        float w2 = __expf(leaky(g_el[s * 3 + 2] + er2) - m2);
        s0 += w0; s1 += w1; s2 += w2;
        const float* fp = feat + (size_t)s * HD + base;
        float2 v0 = *(const float2*)(fp + 0);
        float2 v1 = *(const float2*)(fp + 2);
        float2 v2 = *(const float2*)(fp + 4);
        float wa0 = h0 == 0 ? w0 : (h0 == 1 ? w1 : w2);
        float wa1 = h1 == 0 ? w0 : (h1 == 1 ? w1 : w2);
        float wa2 = h2 == 0 ? w0 : (h2 == 1 ? w1 : w2);
        float wa3 = h3 == 0 ? w0 : (h3 == 1 ? w1 : w2);
        float wa4 = h4 == 0 ? w0 : (h4 == 1 ? w1 : w2);
        float wa5 = h5 == 0 ? w0 : (h5 == 1 ? w1 : w2);
        acc0 += wa0 * v0.x; acc1 += wa1 * v0.y;
        acc2 += wa2 * v1.x; acc3 += wa3 * v1.y;
        acc4 += wa4 * v2.x; acc5 += wa5 * v2.y;
    }
    float i0 = 0.f, i1 = 0.f, i2 = 0.f;
    if (end > beg) { i0 = 1.f / s0; i1 = 1.f / s1; i2 = 1.f / s2; }
    float ia0 = h0 == 0 ? i0 : (h0 == 1 ? i1 : i2);
    float ia1 = h1 == 0 ? i0 : (h1 == 1 ? i1 : i2);
    float ia2 = h2 == 0 ? i0 : (h2 == 1 ? i1 : i2);
    float ia3 = h3 == 0 ? i0 : (h3 == 1 ? i1 : i2);
    float ia4 = h4 == 0 ? i0 : (h4 == 1 ? i1 : i2);
    float ia5 = h5 == 0 ? i0 : (h5 == 1 ? i1 : i2);
    float* op = out + (size_t)warp * HD + base;
    op[0] = fmaxf(acc0 * ia0 + bias[base + 0], 0.f);
    op[1] = fmaxf(acc1 * ia1 + bias[base + 1], 0.f);
    op[2] = fmaxf(acc2 * ia2 + bias[base + 2], 0.f);
    op[3] = fmaxf(acc3 * ia3 + bias[base + 3], 0.f);
    op[4] = fmaxf(acc4 * ia4 + bias[base + 4], 0.f);
    op[5] = fmaxf(acc5 * ia5 + bias[base + 5], 0.f);
}

// ---------------- host launch ----------------
extern "C" void kernel_launch(void* const* d_in, const int* in_sizes, int n_in,
                              void* d_out, int out_size) {
    const float* features = (const float*)d_in[0];
    const int*   src      = (const int*)d_in[1];
    const int*   dst      = (const int*)d_in[2];
    const float* W1  = (const float*)d_in[3];
    const float* al1 = (const float*)d_in[4];
    const float* ar1 = (const float*)d_in[5];
    const float* b1  = (const float*)d_in[6];
    const float* W2  = (const float*)d_in[7];
    const float* al2 = (const float*)d_in[8];
    const float* ar2 = (const float*)d_in[9];
    const float* b2  = (const float*)d_in[10];
    const float* Wm1 = (const float*)d_in[11];
    const float* bm1 = (const float*)d_in[12];
    const float* Wm2 = (const float*)d_in[13];
    const float* bm2 = (const float*)d_in[14];
    float* out = (float*)d_out;

    float *feat, *x, *hid;
    int *cnt;
    cudaGetSymbolAddress((void**)&feat, g_feat);
    cudaGetSymbolAddress((void**)&x, g_x);
    cudaGetSymbolAddress((void**)&hid, g_hid);
    cudaGetSymbolAddress((void**)&cnt, g_cnt);

    const int EB = (N_EDGES + 255) / 256;
    const int WB = (N_NODES * 32 + 255) / 256;  // one warp per node, 256-thread blocks
    const int GM = (N_NODES + 127) / 128;

    // CSR build (graph is the same for both layers)
    cudaMemsetAsync(cnt, 0, N_NODES * sizeof(int));
    hist_k<<<EB, 256>>>(dst);
    scan_k<<<1, 1024>>>();
    cudaMemsetAsync(cnt, 0, N_NODES * sizeof(int));
    scatter_k<<<EB, 256>>>(src, dst);

    // ---- GAT layer 1 (el/er fused into GEMM epilogue) ----
    gemm_k<<<dim3(GM, 3), 128>>>(features, W1, feat, N_NODES, HD, IN_FEATS, nullptr, 0, al1, ar1);
    agg_k<<<WB, 256>>>(feat, b1, x);

    // ---- GAT layer 2 ----
    gemm_k<<<dim3(GM, 3), 128>>>(x, W2, feat, N_NODES, HD, HD, nullptr, 0, al2, ar2);
    agg_k<<<WB, 256>>>(feat, b2, x);

    // ---- MLP head ----
    gemm_k<<<dim3(GM, 1), 128>>>(x, Wm1, hid, N_NODES, HID, HD, bm1, 1, nullptr, nullptr);
    gemm_k<<<dim3(GM, 1), 128>>>(hid, Wm2, out, N_NODES, OUT_FEATS, HID, bm2, 0, nullptr, nullptr);
}

// round 3
// speedup vs baseline: 1.1808x; 1.0332x over previous
#include <cuda_runtime.h>
#include <cuda_bf16.h>
#include <math.h>

#define N_NODES   50000
#define N_EDGES   800000
#define IN_FEATS  256
#define HID       64
#define HEADS     3
#define HD        192   // HEADS*HID
#define OUT_FEATS 64
#define NEG_SLOPE 0.2f

typedef unsigned long long ull;

// ---------------- device scratch (no allocs allowed) ----------------
__device__ float g_feat[(size_t)N_NODES * HD];
__device__ float g_x[(size_t)N_NODES * HD];
__device__ float g_hid[(size_t)N_NODES * HID];
__device__ float g_el[(size_t)N_NODES * HEADS];
__device__ float g_er[(size_t)N_NODES * HEADS];
__device__ int   g_rowptr[N_NODES + 1];
__device__ int   g_cnt[N_NODES];
__device__ int   g_srcs[N_EDGES];

// ---------------- CSR build ----------------
__global__ void hist_k(const int* __restrict__ dst) {
    int e = blockIdx.x * blockDim.x + threadIdx.x;
    if (e < N_EDGES) atomicAdd(&g_cnt[dst[e]], 1);
}

__global__ void scan_k() {
    __shared__ int part[1024];
    int t = threadIdx.x;
    const int chunk = (N_NODES + 1023) / 1024;
    int beg = t * chunk;
    int end = min(beg + chunk, N_NODES);
    int s = 0;
    for (int i = beg; i < end; i++) s += g_cnt[i];
    part[t] = s;
    __syncthreads();
    for (int off = 1; off < 1024; off <<= 1) {
        int v = 0;
        if (t >= off) v = part[t - off];
        __syncthreads();
        part[t] += v;
        __syncthreads();
    }
    int run = (t == 0) ? 0 : part[t - 1];
    for (int i = beg; i < end; i++) { g_rowptr[i] = run; run += g_cnt[i]; }
    if (t == 1023) g_rowptr[N_NODES] = part[1023];
}

__global__ void scatter_k(const int* __restrict__ src, const int* __restrict__ dst) {
    int e = blockIdx.x * blockDim.x + threadIdx.x;
    if (e < N_EDGES) {
        int d = dst[e];
        int pos = atomicAdd(&g_cnt[d], 1);
        g_srcs[g_rowptr[d] + pos] = src[e];
    }
}

// ---------------- packed-f32x2 SGEMM 128x64 tile, 8x8 microtile, 128 threads --
union U4 { float4 f; ull p[2]; };
union U2 { ull p; float2 f; };

__device__ __forceinline__ ull dupf(float a) {
    ull r;
    asm("mov.b64 %0, {%1, %1};" : "=l"(r) : "f"(a));
    return r;
}
__device__ __forceinline__ void ffma2(ull& d, ull a, ull b) {
    asm("fma.rn.f32x2 %0, %1, %2, %0;" : "+l"(d) : "l"(a), "l"(b));
}

// C[M,N] = A[M,K] @ B[K,N] (+bias)(+relu). BN=64 per blockIdx.y.
// If al != null: also write g_el/g_er for head = blockIdx.y.
template<int K>
__global__ void __launch_bounds__(128)
gemm_k(const float* __restrict__ A, const float* __restrict__ B,
       float* __restrict__ C, int M, int N,
       const float* __restrict__ bias, int act,
       const float* __restrict__ al, const float* __restrict__ ar) {
    __shared__ float As[2][16][128];   // [buf][k][m]
    __shared__ float Bs[2][16][64];    // [buf][k][n]
    const int tid = threadIdx.x;
    const int tm = tid >> 3;        // 0..15
    const int tn = tid & 7;         // 0..7
    const int bm = blockIdx.x * 128;
    const int bn = blockIdx.y * 64;

    ull accP[8][4];
#pragma unroll
    for (int i = 0; i < 8; i++)
#pragma unroll
        for (int j = 0; j < 4; j++) accP[i][j] = 0ull;

    const int garow = bm + tid;
    const float* aptr = A + (size_t)garow * K;
    const bool arow_ok = garow < M;

    float4 av[4], bv[2];
    // prefetch tile 0
#pragma unroll
    for (int i = 0; i < 4; i++)
        av[i] = arow_ok ? *(const float4*)(aptr + i * 4) : make_float4(0.f, 0.f, 0.f, 0.f);
#pragma unroll
    for (int i = 0; i < 2; i++) {
        int fid = tid + i * 128;
        int br = fid >> 4, c4 = (fid & 15) << 2;
        bv[i] = *(const float4*)&B[(size_t)br * N + bn + c4];
    }

    const int T = K / 16;
#pragma unroll 1
    for (int t = 0; t < T; t++) {
        const int buf = t & 1;
        // store current tile
#pragma unroll
        for (int i = 0; i < 4; i++) {
            As[buf][i * 4 + 0][tid] = av[i].x;
            As[buf][i * 4 + 1][tid] = av[i].y;
            As[buf][i * 4 + 2][tid] = av[i].z;
            As[buf][i * 4 + 3][tid] = av[i].w;
        }
#pragma unroll
        for (int i = 0; i < 2; i++) {
            int fid = tid + i * 128;
            int br = fid >> 4, c4 = (fid & 15) << 2;
            *(float4*)&Bs[buf][br][c4] = bv[i];
        }
        __syncthreads();
        // prefetch next tile
        if (t + 1 < T) {
            int k0 = (t + 1) * 16;
#pragma unroll
            for (int i = 0; i < 4; i++)
                av[i] = arow_ok ? *(const float4*)(aptr + k0 + i * 4)
                                : make_float4(0.f, 0.f, 0.f, 0.f);
#pragma unroll
            for (int i = 0; i < 2; i++) {
                int fid = tid + i * 128;
                int br = fid >> 4, c4 = (fid & 15) << 2;
                bv[i] = *(const float4*)&B[(size_t)(k0 + br) * N + bn + c4];
            }
        }
        // compute
#pragma unroll
        for (int k = 0; k < 16; k++) {
            U4 a0, a1, b0, b1;
            a0.f = *(const float4*)&As[buf][k][tm * 4];
            a1.f = *(const float4*)&As[buf][k][tm * 4 + 64];
            b0.f = *(const float4*)&Bs[buf][k][tn * 4];
            b1.f = *(const float4*)&Bs[buf][k][tn * 4 + 32];
            ull bp[4] = {b0.p[0], b0.p[1], b1.p[0], b1.p[1]};
            float a[8] = {a0.f.x, a0.f.y, a0.f.z, a0.f.w,
                          a1.f.x, a1.f.y, a1.f.z, a1.f.w};
#pragma unroll
            for (int i = 0; i < 8; i++) {
                ull ad = dupf(a[i]);
#pragma unroll
                for (int jp = 0; jp < 4; jp++) ffma2(accP[i][jp], ad, bp[jp]);
            }
        }
        // next store waits at the next iteration's implicit position; one sync/iter
        __syncthreads();
    }

    // unpack accumulators: col j (0..7) -> global col tn*4 + (j<4 ? j : 32+j-4)
    float acc[8][8];
#pragma unroll
    for (int i = 0; i < 8; i++)
#pragma unroll
        for (int jp = 0; jp < 4; jp++) {
            U2 u; u.p = accP[i][jp];
            int j0 = (jp < 2) ? jp * 2 : 4 + (jp - 2) * 2;
            acc[i][j0] = u.f.x;
            acc[i][j0 + 1] = u.f.y;
        }

    // epilogue
    float elp[8], erp[8], alv[8], arv[8], bvv[8];
    const int head = blockIdx.y;
    if (al) {
#pragma unroll
        for (int j = 0; j < 8; j++) {
            int c = tn * 4 + ((j < 4) ? j : 32 + (j - 4));
            alv[j] = __ldg(&al[head * 64 + c]);
            arv[j] = __ldg(&ar[head * 64 + c]);
        }
#pragma unroll
        for (int i = 0; i < 8; i++) { elp[i] = 0.f; erp[i] = 0.f; }
    }
    if (bias) {
#pragma unroll
        for (int j = 0; j < 8; j++) {
            int c = tn * 4 + ((j < 4) ? j : 32 + (j - 4));
            bvv[j] = __ldg(&bias[bn + c]);
        }
    }
#pragma unroll
    for (int i = 0; i < 8; i++) {
        int gr = bm + tm * 4 + ((i < 4) ? i : 64 + (i - 4));
        float v[8];
#pragma unroll
        for (int j = 0; j < 8; j++) {
            float t = acc[i][j];
            if (bias) t += bvv[j];
            if (act) t = fmaxf(t, 0.f);
            v[j] = t;
            if (al) { elp[i] += t * alv[j]; erp[i] += t * arv[j]; }
        }
        if (gr < M) {
            float* cp = C + (size_t)gr * N + bn;
            *(float4*)(cp + tn * 4)      = make_float4(v[0], v[1], v[2], v[3]);
            *(float4*)(cp + tn * 4 + 32) = make_float4(v[4], v[5], v[6], v[7]);
        }
    }
    if (al) {
#pragma unroll
        for (int off = 1; off < 8; off <<= 1) {
#pragma unroll
            for (int i = 0; i < 8; i++) {
                elp[i] += __shfl_xor_sync(0xFFFFFFFFu, elp[i], off);
                erp[i] += __shfl_xor_sync(0xFFFFFFFFu, erp[i], off);
            }
        }
        if (tn == 0) {
#pragma unroll
            for (int i = 0; i < 8; i++) {
                int gr = bm + tm * 4 + ((i < 4) ? i : 64 + (i - 4));
                if (gr < M) {
                    g_el[gr * 3 + head] = elp[i];
                    g_er[gr * 3 + head] = erp[i];
                }
            }
        }
    }
}

__device__ __forceinline__ float leaky(float x) { return x > 0.f ? x : NEG_SLOPE * x; }

// ---------------- edge-softmax + aggregation: one warp per dst node ----------------
__global__ void agg_k(const float* __restrict__ feat, const float* __restrict__ bias,
                      float* __restrict__ out) {
    int warp = (blockIdx.x * blockDim.x + threadIdx.x) >> 5;
    int lane = threadIdx.x & 31;
    if (warp >= N_NODES) return;
    int beg = g_rowptr[warp], end = g_rowptr[warp + 1];
    float er0 = g_er[warp * 3 + 0];
    float er1 = g_er[warp * 3 + 1];
    float er2 = g_er[warp * 3 + 2];

    float m0 = -1e30f, m1 = -1e30f, m2 = -1e30f;
    for (int i = beg + lane; i < end; i += 32) {
        int s = g_srcs[i];
        m0 = fmaxf(m0, leaky(g_el[s * 3 + 0] + er0));
        m1 = fmaxf(m1, leaky(g_el[s * 3 + 1] + er1));
        m2 = fmaxf(m2, leaky(g_el[s * 3 + 2] + er2));
    }
#pragma unroll
    for (int off = 16; off; off >>= 1) {
        m0 = fmaxf(m0, __shfl_xor_sync(0xFFFFFFFFu, m0, off));
        m1 = fmaxf(m1, __shfl_xor_sync(0xFFFFFFFFu, m1, off));
        m2 = fmaxf(m2, __shfl_xor_sync(0xFFFFFFFFu, m2, off));
    }

    int base = lane * 6;
    int h0 = (base + 0) >> 6, h1 = (base + 1) >> 6, h2 = (base + 2) >> 6;
    int h3 = (base + 3) >> 6, h4 = (base + 4) >> 6, h5 = (base + 5) >> 6;
    float acc0 = 0.f, acc1 = 0.f, acc2 = 0.f, acc3 = 0.f, acc4 = 0.f, acc5 = 0.f;
    float s0 = 0.f, s1 = 0.f, s2 = 0.f;
    int sNext = (beg < end) ? g_srcs[beg] : 0;
    for (int i = beg; i < end; i++) {
        int s = sNext;
        if (i + 1 < end) sNext = g_srcs[i + 1];
        float w0 = __expf(leaky(g_el[s * 3 + 0] + er0) - m0);
        float w1 = __expf(leaky(g_el[s * 3 + 1] + er1) - m1);
        float w2 = __expf(leaky(g_el[s * 3 + 2] + er2) - m2);
        s0 += w0; s1 += w1; s2 += w2;
        const float* fp = feat + (size_t)s * HD + base;
        float2 v0 = *(const float2*)(fp + 0);
        float2 v1 = *(const float2*)(fp + 2);
        float2 v2 = *(const float2*)(fp + 4);
        float wa0 = h0 == 0 ? w0 : (h0 == 1 ? w1 : w2);
        float wa1 = h1 == 0 ? w0 : (h1 == 1 ? w1 : w2);
        float wa2 = h2 == 0 ? w0 : (h2 == 1 ? w1 : w2);
        float wa3 = h3 == 0 ? w0 : (h3 == 1 ? w1 : w2);
        float wa4 = h4 == 0 ? w0 : (h4 == 1 ? w1 : w2);
        float wa5 = h5 == 0 ? w0 : (h5 == 1 ? w1 : w2);
        acc0 += wa0 * v0.x; acc1 += wa1 * v0.y;
        acc2 += wa2 * v1.x; acc3 += wa3 * v1.y;
        acc4 += wa4 * v2.x; acc5 += wa5 * v2.y;
    }
    float i0 = 0.f, i1 = 0.f, i2 = 0.f;
    if (end > beg) { i0 = 1.f / s0; i1 = 1.f / s1; i2 = 1.f / s2; }
    float ia0 = h0 == 0 ? i0 : (h0 == 1 ? i1 : i2);
    float ia1 = h1 == 0 ? i0 : (h1 == 1 ? i1 : i2);
    float ia2 = h2 == 0 ? i0 : (h2 == 1 ? i1 : i2);
    float ia3 = h3 == 0 ? i0 : (h3 == 1 ? i1 : i2);
    float ia4 = h4 == 0 ? i0 : (h4 == 1 ? i1 : i2);
    float ia5 = h5 == 0 ? i0 : (h5 == 1 ? i1 : i2);
    float* op = out + (size_t)warp * HD + base;
    op[0] = fmaxf(acc0 * ia0 + bias[base + 0], 0.f);
    op[1] = fmaxf(acc1 * ia1 + bias[base + 1], 0.f);
    op[2] = fmaxf(acc2 * ia2 + bias[base + 2], 0.f);
    op[3] = fmaxf(acc3 * ia3 + bias[base + 3], 0.f);
    op[4] = fmaxf(acc4 * ia4 + bias[base + 4], 0.f);
    op[5] = fmaxf(acc5 * ia5 + bias[base + 5], 0.f);
}

// ---------------- host launch ----------------
extern "C" void kernel_launch(void* const* d_in, const int* in_sizes, int n_in,
                              void* d_out, int out_size) {
    const float* features = (const float*)d_in[0];
    const int*   src      = (const int*)d_in[1];
    const int*   dst      = (const int*)d_in[2];
    const float* W1  = (const float*)d_in[3];
    const float* al1 = (const float*)d_in[4];
    const float* ar1 = (const float*)d_in[5];
    const float* b1  = (const float*)d_in[6];
    const float* W2  = (const float*)d_in[7];
    const float* al2 = (const float*)d_in[8];
    const float* ar2 = (const float*)d_in[9];
    const float* b2  = (const float*)d_in[10];
    const float* Wm1 = (const float*)d_in[11];
    const float* bm1 = (const float*)d_in[12];
    const float* Wm2 = (const float*)d_in[13];
    const float* bm2 = (const float*)d_in[14];
    float* out = (float*)d_out;

    float *feat, *x, *hid;
    int *cnt;
    cudaGetSymbolAddress((void**)&feat, g_feat);
    cudaGetSymbolAddress((void**)&x, g_x);
    cudaGetSymbolAddress((void**)&hid, g_hid);
    cudaGetSymbolAddress((void**)&cnt, g_cnt);

    const int EB = (N_EDGES + 255) / 256;
    const int WB = (N_NODES * 32 + 255) / 256;
    const int GM = (N_NODES + 127) / 128;

    cudaMemsetAsync(cnt, 0, N_NODES * sizeof(int));
    hist_k<<<EB, 256>>>(dst);
    scan_k<<<1, 1024>>>();
    cudaMemsetAsync(cnt, 0, N_NODES * sizeof(int));
    scatter_k<<<EB, 256>>>(src, dst);

    // ---- GAT layer 1 (el/er fused into GEMM epilogue) ----
    gemm_k<IN_FEATS><<<dim3(GM, 3), 128>>>(features, W1, feat, N_NODES, HD, nullptr, 0, al1, ar1);
    agg_k<<<WB, 256>>>(feat, b1, x);

    // ---- GAT layer 2 ----
    gemm_k<HD><<<dim3(GM, 3), 128>>>(x, W2, feat, N_NODES, HD, nullptr, 0, al2, ar2);
    agg_k<<<WB, 256>>>(feat, b2, x);

    // ---- MLP head ----
    gemm_k<HD><<<dim3(GM, 1), 128>>>(x, Wm1, hid, N_NODES, HID, bm1, 1, nullptr, nullptr);
    gemm_k<HID><<<dim3(GM, 1), 128>>>(hid, Wm2, out, N_NODES, OUT_FEATS, bm2, 0, nullptr, nullptr);
}